// round 5
// baseline (speedup 1.0000x reference)
#include <cuda_runtime.h>
#include <cuda_fp16.h>
#include <stdint.h>
#include <math.h>

#define NP 512
#define MP 512
#define DD 1024
#define H1C 512
#define H2C 256
#define NPAIR (NP*MP)
#define STRB 80   // bytes per 32-half smem row (64B data + 16B pad)

// Scratch
__device__ __half g_h1[(size_t)NPAIR * H1C];   // 256 MB fp16 activations
__device__ __half g_w1h[H1C * DD];
__device__ __half g_w2h[H2C * H1C];
__device__ float  g_d[NPAIR];                  // finished (negated) logits
__device__ float  g_cost[NPAIR];

__device__ __forceinline__ float lrelu(float x){ return x >= 0.f ? x : 0.01f*x; }
__device__ __forceinline__ uint32_t smem_u32(const void* p){
    uint32_t a;
    asm("{ .reg .u64 t; cvta.to.shared.u64 t, %1; cvt.u32.u64 %0, t; }" : "=r"(a) : "l"(p));
    return a;
}
#define CP16(dst, src) asm volatile("cp.async.cg.shared.global [%0], [%1], 16;" :: "r"(dst), "l"(src))
#define CP_COMMIT() asm volatile("cp.async.commit_group;" ::: "memory")
#define CP_WAIT2()  asm volatile("cp.async.wait_group 2;" ::: "memory")

__device__ __forceinline__ void ldmat4(uint32_t* r, uint32_t addr){
    asm volatile("ldmatrix.sync.aligned.m8n8.x4.shared.b16 {%0,%1,%2,%3}, [%4];"
        : "=r"(r[0]),"=r"(r[1]),"=r"(r[2]),"=r"(r[3]) : "r"(addr));
}
__device__ __forceinline__ void mma_f16(float* c, const uint32_t* a, const uint32_t* b){
    asm volatile("mma.sync.aligned.m16n8k16.row.col.f32.f16.f16.f32 "
        "{%0,%1,%2,%3}, {%4,%5,%6,%7}, {%8,%9}, {%0,%1,%2,%3};"
        : "+f"(c[0]),"+f"(c[1]),"+f"(c[2]),"+f"(c[3])
        : "r"(a[0]),"r"(a[1]),"r"(a[2]),"r"(a[3]), "r"(b[0]),"r"(b[1]));
}

// Mainloop compute: CTA 128x256, warp tile 64x64, BK=32.
// All fragments (both k16 steps) loaded up front -> big scheduling window.
__device__ __forceinline__ void compute_tile64(uint32_t sa, uint32_t sb,
        int wm, int wn, int rA, int cAd, float acc[4][8][4]){
    uint32_t a[2][4][4], b[2][8][2];
#pragma unroll
    for (int ks = 0; ks < 2; ks++){
#pragma unroll
        for (int mt = 0; mt < 4; mt++)
            ldmat4(a[ks][mt], sa + (uint32_t)((64*wm + 16*mt + rA)*STRB + (2*ks + cAd)*16));
#pragma unroll
        for (int p = 0; p < 4; p++){
            uint32_t r[4];
            ldmat4(r, sb + (uint32_t)((64*wn + 16*p + rA)*STRB + (2*ks + cAd)*16));
            b[ks][2*p][0] = r[0]; b[ks][2*p+1][0] = r[1];
            b[ks][2*p][1] = r[2]; b[ks][2*p+1][1] = r[3];
        }
    }
#pragma unroll
    for (int ks = 0; ks < 2; ks++)
#pragma unroll
        for (int mt = 0; mt < 4; mt++)
#pragma unroll
            for (int nt = 0; nt < 8; nt++)
                mma_f16(acc[mt][nt], a[ks][mt], b[ks][nt]);
}

// ---------------------------------------------------------------------------
__global__ void k_conv(const float* __restrict__ W1, const float* __restrict__ W2){
    const int stride = gridDim.x * blockDim.x;
    const int i0 = blockIdx.x*blockDim.x + threadIdx.x;
    for (int i = i0; i < H1C*DD; i += stride) g_w1h[i] = __float2half(W1[i]);
    for (int i = i0; i < H2C*H1C; i += stride) g_w2h[i] = __float2half(W2[i]);
}

// Filler so k_layer1 is the ncu-profiled launch (index 3)
__global__ void k_nop(){}

// ---------------------------------------------------------------------------
// Layer 1: GEMM [262144 x 512], K=1024.  CTA 128x256.  A = diff^2 on the fly.
// smem: A 2 x 10240  |  B 4 x 20480   (dynamic, 102400 B)
// ---------------------------------------------------------------------------
#define L1_SMEM (2*10240 + 4*20480)

__global__ __launch_bounds__(256,1) void k_layer1(
    const float* __restrict__ Maug, const float* __restrict__ Q,
    const float* __restrict__ b1)
{
    extern __shared__ __align__(16) char smem[];
    const int tid = threadIdx.x, lane = tid & 31, wid = tid >> 5;
    const int h0 = blockIdx.x * 256;
    const int r0 = blockIdx.y * 128;
    const int n  = r0 >> 9;
    const int m0 = r0 & 511;
    const int wm = wid & 1, wn = wid >> 1;
    const int rA = lane & 15, cAd = lane >> 4;
    const int kq = tid & 7,  rb  = tid >> 3;

    const uint32_t sbase = smem_u32(smem);
    const uint32_t sAu0 = sbase, sAu1 = sbase + 10240;
    const uint32_t sBu  = sbase + 20480;

    const float4* Q4 = (const float4*)Q;
    const float4* M4 = (const float4*)Maug;

    float acc[4][8][4];
#pragma unroll
    for (int i=0;i<4;i++)
#pragma unroll
    for (int j=0;j<8;j++)
#pragma unroll
    for (int k=0;k<4;k++) acc[i][j][k] = 0.f;
    float creg[4] = {0.f,0.f,0.f,0.f};

    float4 qv[4], mv;

    auto ldQ = [&](int c){
        mv = M4[n*(DD/4) + c*8 + kq];
#pragma unroll
        for (int j = 0; j < 4; j++)
            qv[j] = Q4[(size_t)(m0 + rb + 32*j)*(DD/4) + c*8 + kq];
    };
    auto stA = [&](uint32_t sAu){
#pragma unroll
        for (int j = 0; j < 4; j++){
            const int row = rb + 32*j;
            float x0 = mv.x - qv[j].x, x1 = mv.y - qv[j].y;
            float x2 = mv.z - qv[j].z, x3 = mv.w - qv[j].w;
            x0 *= x0; x1 *= x1; x2 *= x2; x3 *= x3;
            creg[j] += (x0 + x1) + (x2 + x3);
            char* p = smem + (sAu - sbase) + row*STRB + kq*8;
            *(__half2*)(p)     = __floats2half2_rn(x0, x1);
            *(__half2*)(p + 4) = __floats2half2_rn(x2, x3);
        }
    };
    auto fillB = [&](int c){
        const uint32_t s = sBu + (uint32_t)(c & 3) * 20480;
#pragma unroll
        for (int jj = 0; jj < 4; jj++){
            const int idx = tid + 256*jj;
            const int row = idx >> 2, ch = idx & 3;
            CP16(s + (uint32_t)(row*STRB + ch*16),
                 g_w1h + (size_t)(h0 + row)*DD + c*32 + ch*8);
        }
    };

    ldQ(0); stA(sAu0);
    fillB(0); CP_COMMIT();
    fillB(1); CP_COMMIT();
    fillB(2); CP_COMMIT();

    for (int c = 0; c < 32; c++){
        const uint32_t sa = (c & 1) ? sAu1 : sAu0;
        if (c + 1 < 32) ldQ(c + 1);          // prefetch Q for next chunk
        CP_WAIT2(); __syncthreads();
        if (c + 3 < 32) fillB(c + 3);        // issue async fill BEFORE compute
        CP_COMMIT();
        compute_tile64(sa, sBu + (uint32_t)(c & 3)*20480, wm, wn, rA, cAd, acc);
        if (c + 1 < 32) stA((c & 1) ? sAu0 : sAu1);
    }

    // fused cost (fp32 exact), reduce over the 8 threads per row
#pragma unroll
    for (int j = 0; j < 4; j++){
        float v = creg[j];
        v += __shfl_xor_sync(0xffffffffu, v, 1);
        v += __shfl_xor_sync(0xffffffffu, v, 2);
        v += __shfl_xor_sync(0xffffffffu, v, 4);
        if (kq == 0 && blockIdx.x == 0)
            g_cost[n*MP + m0 + rb + 32*j] = v;
    }

    // epilogue: bias + leaky relu, store fp16
    const int g = lane >> 2, tg = lane & 3;
#pragma unroll
    for (int nt = 0; nt < 8; nt++){
        const int col = h0 + 64*wn + 8*nt + 2*tg;
        const float b0v = b1[col], b1v = b1[col+1];
#pragma unroll
        for (int mt = 0; mt < 4; mt++){
            const int row = r0 + 64*wm + 16*mt + g;
            *(__half2*)&g_h1[(size_t)row*H1C + col] =
                __floats2half2_rn(lrelu(acc[mt][nt][0]+b0v), lrelu(acc[mt][nt][1]+b1v));
            *(__half2*)&g_h1[(size_t)(row+8)*H1C + col] =
                __floats2half2_rn(lrelu(acc[mt][nt][2]+b0v), lrelu(acc[mt][nt][3]+b1v));
        }
    }
}

// ---------------------------------------------------------------------------
// Layer 2+3: GEMM [262144 x 256], K=512, CTA 128x256 (full N).  Epilogue
// applies bias+lrelu, dots with W3, writes finished negated logit.
// smem: A 4 x 10240 | B 4 x 20480  (dynamic, 122880 B)
// ---------------------------------------------------------------------------
#define L2_SMEM (4*10240 + 4*20480)

__global__ __launch_bounds__(256,1) void k_layer2(
    const float* __restrict__ b2, const float* __restrict__ W3,
    const float* __restrict__ b3)
{
    extern __shared__ __align__(16) char smem[];
    const int tid = threadIdx.x, lane = tid & 31, wid = tid >> 5;
    const int r0 = blockIdx.x * 128;
    const int wm = wid & 1, wn = wid >> 1;
    const int rA = lane & 15, cAd = lane >> 4;

    const uint32_t sbase = smem_u32(smem);
    const uint32_t sAu = sbase;
    const uint32_t sBu = sbase + 4*10240;

    float acc[4][8][4];
#pragma unroll
    for (int i=0;i<4;i++)
#pragma unroll
    for (int j=0;j<8;j++)
#pragma unroll
    for (int k=0;k<4;k++) acc[i][j][k] = 0.f;

    auto fill = [&](int c){
        const uint32_t st = (uint32_t)(c & 3);
        const uint32_t sa = sAu + st*10240, sb = sBu + st*20480;
#pragma unroll
        for (int jj = 0; jj < 2; jj++){
            const int idx = tid + 256*jj;
            const int row = idx >> 2, ch = idx & 3;
            CP16(sa + (uint32_t)(row*STRB + ch*16),
                 g_h1 + (size_t)(r0 + row)*H1C + c*32 + ch*8);
        }
#pragma unroll
        for (int jj = 0; jj < 4; jj++){
            const int idx = tid + 256*jj;
            const int row = idx >> 2, ch = idx & 3;
            CP16(sb + (uint32_t)(row*STRB + ch*16),
                 g_w2h + (size_t)row*H1C + c*32 + ch*8);
        }
    };

    fill(0); CP_COMMIT();
    fill(1); CP_COMMIT();
    fill(2); CP_COMMIT();

    for (int c = 0; c < 16; c++){
        const uint32_t st = (uint32_t)(c & 3);
        CP_WAIT2(); __syncthreads();
        if (c + 3 < 16) fill(c + 3);         // async fill BEFORE compute
        CP_COMMIT();
        compute_tile64(sAu + st*10240, sBu + st*20480, wm, wn, rA, cAd, acc);
    }

    // epilogue: bias + lrelu + W3 dot (fp32)
    const int g = lane >> 2, tg = lane & 3;
    float dot[4][2];
#pragma unroll
    for (int mt=0; mt<4; mt++){ dot[mt][0]=0.f; dot[mt][1]=0.f; }
#pragma unroll
    for (int nt = 0; nt < 8; nt++){
        const int col = 64*wn + 8*nt + 2*tg;
        const float b0v = b2[col], b1v = b2[col+1];
        const float w0 = W3[col],  w1 = W3[col+1];
#pragma unroll
        for (int mt = 0; mt < 4; mt++){
            dot[mt][0] += lrelu(acc[mt][nt][0]+b0v)*w0 + lrelu(acc[mt][nt][1]+b1v)*w1;
            dot[mt][1] += lrelu(acc[mt][nt][2]+b0v)*w0 + lrelu(acc[mt][nt][3]+b1v)*w1;
        }
    }
    // reduce across tg (shfl) then across the 4 wn warps (smem)
    float* spart = (float*)smem;   // reuse stage-A region post-mainloop
    __syncthreads();
#pragma unroll
    for (int mt = 0; mt < 4; mt++)
#pragma unroll
        for (int hh = 0; hh < 2; hh++){
            float v = dot[mt][hh];
            v += __shfl_xor_sync(0xffffffffu, v, 1);
            v += __shfl_xor_sync(0xffffffffu, v, 2);
            if (tg == 0) spart[(64*wm + 16*mt + 8*hh + g)*4 + wn] = v;
        }
    __syncthreads();
    if (tid < 128){
        const float v = spart[tid*4+0] + spart[tid*4+1] + spart[tid*4+2] + spart[tid*4+3];
        g_d[r0 + tid] = -(v + b3[0]);
    }
}

// ---------------------------------------------------------------------------
// Softmax over n (per m) + weighted reductions
// ---------------------------------------------------------------------------
__global__ __launch_bounds__(512) void k_reduce(
    const int* __restrict__ nfg_p, float* __restrict__ out)
{
    __shared__ float sm[512];
    const int m = blockIdx.x, n = threadIdx.x;
    const float v = g_d[n * MP + m];

    sm[n] = v; __syncthreads();
    for (int s = 256; s; s >>= 1) {
        if (n < s) sm[n] = fmaxf(sm[n], sm[n + s]);
        __syncthreads();
    }
    const float mx = sm[0]; __syncthreads();

    const float p = expf(v - mx);
    sm[n] = p; __syncthreads();
    for (int s = 256; s; s >>= 1) {
        if (n < s) sm[n] += sm[n + s];
        __syncthreads();
    }
    const float Z = sm[0]; __syncthreads();

    const float sval = g_cost[n * MP + m] * (p / Z);
    sm[n] = sval; __syncthreads();
    for (int s = 256; s; s >>= 1) {
        if (n < s) sm[n] += sm[n + s];
        __syncthreads();
    }
    const float score = sm[0]; __syncthreads();

    const int nfg = *nfg_p;
    sm[n] = (n < nfg) ? sval : 0.f; __syncthreads();
    for (int s = 256; s; s >>= 1) {
        if (n < s) sm[n] += sm[n + s];
        __syncthreads();
    }
    if (n == 0) {
        out[m]      = score;
        out[MP + m] = sm[0];
    }
}

// ---------------------------------------------------------------------------
extern "C" void kernel_launch(void* const* d_in, const int* in_sizes, int n_in,
                              void* d_out, int out_size)
{
    const float* Maug = (const float*)d_in[0];
    const float* Q    = (const float*)d_in[1];
    const float* W1   = (const float*)d_in[2];
    const float* b1   = (const float*)d_in[3];
    const float* W2   = (const float*)d_in[4];
    const float* b2   = (const float*)d_in[5];
    const float* W3   = (const float*)d_in[6];
    const float* b3   = (const float*)d_in[7];
    const int*   nfg  = (const int*)d_in[8];
    float* out = (float*)d_out;

    cudaFuncSetAttribute(k_layer1, cudaFuncAttributeMaxDynamicSharedMemorySize, L1_SMEM);
    cudaFuncSetAttribute(k_layer2, cudaFuncAttributeMaxDynamicSharedMemorySize, L2_SMEM);

    k_conv  <<<512, 256>>>(W1, W2);
    k_nop   <<<1, 32>>>();    // fillers: put k_layer1 at launch index 3
    k_nop   <<<1, 32>>>();    // (ncu profiles the 4th launch)
    k_layer1<<<dim3(H1C/256, NPAIR/128), 256, L1_SMEM>>>(Maug, Q, b1);
    k_layer2<<<NPAIR/128, 256, L2_SMEM>>>(b2, W3, b3);
    k_reduce<<<MP, 512>>>(nfg, out);
}

// round 6
// speedup vs baseline: 1.0475x; 1.0475x over previous
#include <cuda_runtime.h>
#include <cuda_fp16.h>
#include <stdint.h>
#include <math.h>

#define NP 512
#define MP 512
#define DD 1024
#define H1C 512
#define H2C 256
#define NPAIR (NP*MP)
#define STRB 80   // bytes per 32-half smem row (64B data + 16B pad)

// Scratch
__device__ __half g_h1[(size_t)NPAIR * H1C];   // 256 MB fp16 activations
__device__ __half g_w1h[H1C * DD];
__device__ __half g_w2h[H2C * H1C];
__device__ __half g_qh[MP * DD];
__device__ __half g_mh[NP * DD];
__device__ float  g_dpart[(size_t)NPAIR * 2];  // per-row logit partials
__device__ float  g_cost[NPAIR];

union U4 { uint4 u; __half2 h[4]; };

__device__ __forceinline__ float lrelu(float x){ return x >= 0.f ? x : 0.01f*x; }
__device__ __forceinline__ uint32_t smem_u32(const void* p){
    uint32_t a;
    asm("{ .reg .u64 t; cvta.to.shared.u64 t, %1; cvt.u32.u64 %0, t; }" : "=r"(a) : "l"(p));
    return a;
}
#define CP16(dst, src) asm volatile("cp.async.cg.shared.global [%0], [%1], 16;" :: "r"(dst), "l"(src))
#define CP_COMMIT() asm volatile("cp.async.commit_group;" ::: "memory")
#define CP_WAIT2()  asm volatile("cp.async.wait_group 2;" ::: "memory")

__device__ __forceinline__ void ldmat4(uint32_t* r, uint32_t addr){
    asm volatile("ldmatrix.sync.aligned.m8n8.x4.shared.b16 {%0,%1,%2,%3}, [%4];"
        : "=r"(r[0]),"=r"(r[1]),"=r"(r[2]),"=r"(r[3]) : "r"(addr));
}
__device__ __forceinline__ void mma_f16(float* c, const uint32_t* a, const uint32_t* b){
    asm volatile("mma.sync.aligned.m16n8k16.row.col.f32.f16.f16.f32 "
        "{%0,%1,%2,%3}, {%4,%5,%6,%7}, {%8,%9}, {%0,%1,%2,%3};"
        : "+f"(c[0]),"+f"(c[1]),"+f"(c[2]),"+f"(c[3])
        : "r"(a[0]),"r"(a[1]),"r"(a[2]),"r"(a[3]), "r"(b[0]),"r"(b[1]));
}

// Warp tile 64x64, BK=32.  wm,wn in {0,1}.
__device__ __forceinline__ void compute_tile64(uint32_t sa, uint32_t sb,
        int wm, int wn, int rA, int cAd, float acc[4][8][4]){
    uint32_t a[2][4][4], b[2][8][2];
#pragma unroll
    for (int ks = 0; ks < 2; ks++){
#pragma unroll
        for (int mt = 0; mt < 4; mt++)
            ldmat4(a[ks][mt], sa + (uint32_t)((64*wm + 16*mt + rA)*STRB + (2*ks + cAd)*16));
#pragma unroll
        for (int p = 0; p < 4; p++){
            uint32_t r[4];
            ldmat4(r, sb + (uint32_t)((64*wn + 16*p + rA)*STRB + (2*ks + cAd)*16));
            b[ks][2*p][0] = r[0]; b[ks][2*p+1][0] = r[1];
            b[ks][2*p][1] = r[2]; b[ks][2*p+1][1] = r[3];
        }
    }
#pragma unroll
    for (int ks = 0; ks < 2; ks++)
#pragma unroll
        for (int mt = 0; mt < 4; mt++)
#pragma unroll
            for (int nt = 0; nt < 8; nt++)
                mma_f16(acc[mt][nt], a[ks][mt], b[ks][nt]);
}

// ---------------------------------------------------------------------------
__global__ void k_conv(const float* __restrict__ W1, const float* __restrict__ W2,
                       const float* __restrict__ Q,  const float* __restrict__ Maug){
    const int stride = gridDim.x * blockDim.x;
    const int i0 = blockIdx.x*blockDim.x + threadIdx.x;
    for (int i = i0; i < H1C*DD; i += stride) g_w1h[i] = __float2half(W1[i]);
    for (int i = i0; i < H2C*H1C; i += stride) g_w2h[i] = __float2half(W2[i]);
    for (int i = i0; i < MP*DD;  i += stride) g_qh[i] = __float2half(Q[i]);
    for (int i = i0; i < NP*DD;  i += stride) g_mh[i] = __float2half(Maug[i]);
}

// Fillers so k_layer1 lands at ncu's profiled launch index (3)
__global__ void k_nop(){}

// ---------------------------------------------------------------------------
// Layer 1: GEMM [262144 x 512], K=1024.  CTA 128x128, 128 thr, 2 CTAs/SM.
// A = diff^2 (half2) on the fly; cost fused (blockIdx.x==0 CTAs only).
// smem: A 2 x 10240 | B 4 x 10240 = 61440
// ---------------------------------------------------------------------------
#define L1_SMEM (2*10240 + 4*10240)

__global__ __launch_bounds__(128,2) void k_layer1(const float* __restrict__ b1)
{
    extern __shared__ __align__(16) char smem[];
    const int tid = threadIdx.x, lane = tid & 31, wid = tid >> 5;
    const int h0 = blockIdx.x * 128;       // 4 col blocks
    const int r0 = blockIdx.y * 128;       // 2048 row blocks
    const int n  = r0 >> 9;
    const int m0 = r0 & 511;
    const int wm = wid & 1, wn = wid >> 1;
    const int rA = lane & 15, cAd = lane >> 4;
    const int kq = tid & 3,  rb  = tid >> 2;   // A-gen: 4 uint4/row, 32 rows/pass
    const bool do_cost = (blockIdx.x == 0);

    const uint32_t sbase = smem_u32(smem);
    const uint32_t sAu0 = sbase, sAu1 = sbase + 10240;
    const uint32_t sBu  = sbase + 20480;

    float acc[4][8][4];
#pragma unroll
    for (int i=0;i<4;i++)
#pragma unroll
    for (int j=0;j<8;j++)
#pragma unroll
    for (int k=0;k<4;k++) acc[i][j][k] = 0.f;
    float creg[4] = {0.f,0.f,0.f,0.f};

    U4 qv[4], mv;

    auto ldQ = [&](int c){
        mv.u = *(const uint4*)&g_mh[(size_t)n*DD + c*32 + kq*8];
#pragma unroll
        for (int j = 0; j < 4; j++)
            qv[j].u = *(const uint4*)&g_qh[(size_t)(m0 + rb + 32*j)*DD + c*32 + kq*8];
    };
    auto stA = [&](uint32_t sAu){
#pragma unroll
        for (int j = 0; j < 4; j++){
            const int row = rb + 32*j;
            U4 s;
#pragma unroll
            for (int i = 0; i < 4; i++){
                __half2 d = __hsub2(mv.h[i], qv[j].h[i]);
                s.h[i] = __hmul2(d, d);
            }
            if (do_cost){
#pragma unroll
                for (int i = 0; i < 4; i++){
                    float2 f = __half22float2(s.h[i]);
                    creg[j] += f.x + f.y;
                }
            }
            *(uint4*)(smem + (sAu - sbase) + row*STRB + kq*16) = s.u;
        }
    };
    auto fillB = [&](int c){
        const uint32_t s = sBu + (uint32_t)(c & 3) * 10240;
#pragma unroll
        for (int jj = 0; jj < 4; jj++){
            const int idx = tid + 128*jj;
            const int row = idx >> 2, ch = idx & 3;
            CP16(s + (uint32_t)(row*STRB + ch*16),
                 g_w1h + (size_t)(h0 + row)*DD + c*32 + ch*8);
        }
    };

    ldQ(0); stA(sAu0);
    fillB(0); CP_COMMIT();
    fillB(1); CP_COMMIT();
    fillB(2); CP_COMMIT();

    for (int c = 0; c < 32; c++){
        const uint32_t sa = (c & 1) ? sAu1 : sAu0;
        if (c + 1 < 32) ldQ(c + 1);
        CP_WAIT2(); __syncthreads();
        if (c + 3 < 32) fillB(c + 3);
        CP_COMMIT();
        compute_tile64(sa, sBu + (uint32_t)(c & 3)*10240, wm, wn, rA, cAd, acc);
        if (c + 1 < 32) stA((c & 1) ? sAu0 : sAu1);
    }

    // fused cost (reduce over the 4 threads per row)
    if (do_cost){
#pragma unroll
        for (int j = 0; j < 4; j++){
            float v = creg[j];
            v += __shfl_xor_sync(0xffffffffu, v, 1);
            v += __shfl_xor_sync(0xffffffffu, v, 2);
            if (kq == 0) g_cost[n*MP + m0 + rb + 32*j] = v;
        }
    }

    // epilogue: bias + leaky relu -> fp16
    const int g = lane >> 2, tg = lane & 3;
#pragma unroll
    for (int nt = 0; nt < 8; nt++){
        const int col = h0 + 64*wn + 8*nt + 2*tg;
        const float b0v = b1[col], b1v = b1[col+1];
#pragma unroll
        for (int mt = 0; mt < 4; mt++){
            const int row = r0 + 64*wm + 16*mt + g;
            *(__half2*)&g_h1[(size_t)row*H1C + col] =
                __floats2half2_rn(lrelu(acc[mt][nt][0]+b0v), lrelu(acc[mt][nt][1]+b1v));
            *(__half2*)&g_h1[(size_t)(row+8)*H1C + col] =
                __floats2half2_rn(lrelu(acc[mt][nt][2]+b0v), lrelu(acc[mt][nt][3]+b1v));
        }
    }
}

// ---------------------------------------------------------------------------
// Layer 2+3: GEMM [262144 x 256], K=512.  CTA 128x128, 128 thr, 2 CTAs/SM.
// Epilogue: bias+lrelu+W3 dot -> per-strip partial logit.
// smem: A 4 x 10240 | B 4 x 10240 = 81920
// ---------------------------------------------------------------------------
#define L2_SMEM (4*10240 + 4*10240)

__global__ __launch_bounds__(128,2) void k_layer2(
    const float* __restrict__ b2, const float* __restrict__ W3)
{
    extern __shared__ __align__(16) char smem[];
    const int tid = threadIdx.x, lane = tid & 31, wid = tid >> 5;
    const int h0 = blockIdx.x * 128;       // 2 col blocks
    const int r0 = blockIdx.y * 128;
    const int wm = wid & 1, wn = wid >> 1;
    const int rA = lane & 15, cAd = lane >> 4;

    const uint32_t sbase = smem_u32(smem);
    const uint32_t sAu = sbase;
    const uint32_t sBu = sbase + 4*10240;

    float acc[4][8][4];
#pragma unroll
    for (int i=0;i<4;i++)
#pragma unroll
    for (int j=0;j<8;j++)
#pragma unroll
    for (int k=0;k<4;k++) acc[i][j][k] = 0.f;

    auto fill = [&](int c){
        const uint32_t st = (uint32_t)(c & 3);
        const uint32_t sa = sAu + st*10240, sb = sBu + st*10240;
#pragma unroll
        for (int jj = 0; jj < 4; jj++){
            const int idx = tid + 128*jj;
            const int row = idx >> 2, ch = idx & 3;
            CP16(sa + (uint32_t)(row*STRB + ch*16),
                 g_h1 + (size_t)(r0 + row)*H1C + c*32 + ch*8);
            CP16(sb + (uint32_t)(row*STRB + ch*16),
                 g_w2h + (size_t)(h0 + row)*H1C + c*32 + ch*8);
        }
    };

    fill(0); CP_COMMIT();
    fill(1); CP_COMMIT();
    fill(2); CP_COMMIT();

    for (int c = 0; c < 16; c++){
        const uint32_t st = (uint32_t)(c & 3);
        CP_WAIT2(); __syncthreads();
        if (c + 3 < 16) fill(c + 3);
        CP_COMMIT();
        compute_tile64(sAu + st*10240, sBu + st*10240, wm, wn, rA, cAd, acc);
    }

    // epilogue: bias + lrelu + W3 dot
    const int g = lane >> 2, tg = lane & 3;
    float dot[4][2];
#pragma unroll
    for (int mt=0; mt<4; mt++){ dot[mt][0]=0.f; dot[mt][1]=0.f; }
#pragma unroll
    for (int nt = 0; nt < 8; nt++){
        const int col = h0 + 64*wn + 8*nt + 2*tg;
        const float b0v = b2[col], b1v = b2[col+1];
        const float w0 = W3[col],  w1 = W3[col+1];
#pragma unroll
        for (int mt = 0; mt < 4; mt++){
            dot[mt][0] += lrelu(acc[mt][nt][0]+b0v)*w0 + lrelu(acc[mt][nt][1]+b1v)*w1;
            dot[mt][1] += lrelu(acc[mt][nt][2]+b0v)*w0 + lrelu(acc[mt][nt][3]+b1v)*w1;
        }
    }
    float* spart = (float*)smem;   // [128][2]
    __syncthreads();
#pragma unroll
    for (int mt = 0; mt < 4; mt++)
#pragma unroll
        for (int hh = 0; hh < 2; hh++){
            float v = dot[mt][hh];
            v += __shfl_xor_sync(0xffffffffu, v, 1);
            v += __shfl_xor_sync(0xffffffffu, v, 2);
            if (tg == 0) spart[(64*wm + 16*mt + 8*hh + g)*2 + wn] = v;
        }
    __syncthreads();
    if (tid < 128){
        g_dpart[(size_t)(r0 + tid)*2 + blockIdx.x] = spart[tid*2+0] + spart[tid*2+1];
    }
}

// ---------------------------------------------------------------------------
// Softmax over n (per m) + weighted reductions
// ---------------------------------------------------------------------------
__global__ __launch_bounds__(512) void k_reduce(
    const int* __restrict__ nfg_p, const float* __restrict__ b3,
    float* __restrict__ out)
{
    __shared__ float sm[512];
    const int m = blockIdx.x, n = threadIdx.x;
    const int r = n*MP + m;
    const float v = -(g_dpart[(size_t)r*2] + g_dpart[(size_t)r*2+1] + b3[0]);

    sm[n] = v; __syncthreads();
    for (int s = 256; s; s >>= 1) {
        if (n < s) sm[n] = fmaxf(sm[n], sm[n + s]);
        __syncthreads();
    }
    const float mx = sm[0]; __syncthreads();

    const float p = expf(v - mx);
    sm[n] = p; __syncthreads();
    for (int s = 256; s; s >>= 1) {
        if (n < s) sm[n] += sm[n + s];
        __syncthreads();
    }
    const float Z = sm[0]; __syncthreads();

    const float sval = g_cost[r] * (p / Z);
    sm[n] = sval; __syncthreads();
    for (int s = 256; s; s >>= 1) {
        if (n < s) sm[n] += sm[n + s];
        __syncthreads();
    }
    const float score = sm[0]; __syncthreads();

    const int nfg = *nfg_p;
    sm[n] = (n < nfg) ? sval : 0.f; __syncthreads();
    for (int s = 256; s; s >>= 1) {
        if (n < s) sm[n] += sm[n + s];
        __syncthreads();
    }
    if (n == 0) {
        out[m]      = score;
        out[MP + m] = sm[0];
    }
}

// ---------------------------------------------------------------------------
extern "C" void kernel_launch(void* const* d_in, const int* in_sizes, int n_in,
                              void* d_out, int out_size)
{
    const float* Maug = (const float*)d_in[0];
    const float* Q    = (const float*)d_in[1];
    const float* W1   = (const float*)d_in[2];
    const float* b1   = (const float*)d_in[3];
    const float* W2   = (const float*)d_in[4];
    const float* b2   = (const float*)d_in[5];
    const float* W3   = (const float*)d_in[6];
    const float* b3   = (const float*)d_in[7];
    const int*   nfg  = (const int*)d_in[8];
    float* out = (float*)d_out;

    cudaFuncSetAttribute(k_layer1, cudaFuncAttributeMaxDynamicSharedMemorySize, L1_SMEM);
    cudaFuncSetAttribute(k_layer2, cudaFuncAttributeMaxDynamicSharedMemorySize, L2_SMEM);

    k_conv  <<<512, 256>>>(W1, W2, Q, Maug);
    k_nop   <<<1, 32>>>();
    k_nop   <<<1, 32>>>();
    k_layer1<<<dim3(H1C/128, NPAIR/128), 128, L1_SMEM>>>(b1);
    k_layer2<<<dim3(H2C/128, NPAIR/128), 128, L2_SMEM>>>(b2, W3);
    k_reduce<<<MP, 512>>>(nfg, b3, out);
}

// round 8
// speedup vs baseline: 1.0598x; 1.0117x over previous
#include <cuda_runtime.h>
#include <cuda_fp16.h>
#include <stdint.h>
#include <math.h>

#define NP 512
#define MP 512
#define DD 1024
#define H1C 512
#define H2C 256
#define NPAIR (NP*MP)
#define STRB 80   // bytes per 32-half smem row (64B data + 16B pad)

// Scratch
__device__ uint4  g_h1f[(size_t)16384 * 32 * 32]; // h1 in fragment-major (256 MB)
__device__ uint4  g_qf[32 * 64 * 32];             // Q fragment-major (1 MB)
__device__ __half g_w1h[H1C * DD];
__device__ __half g_w2h[H2C * H1C];
__device__ __half g_mh[NP * DD];
__device__ float  g_dpart[(size_t)NPAIR * 2];
__device__ float  g_cost[NPAIR];

union U4 { uint4 u; __half2 h[4]; };

__device__ __forceinline__ float lrelu(float x){ return x >= 0.f ? x : 0.01f*x; }
__device__ __forceinline__ uint32_t smem_u32(const void* p){
    uint32_t a;
    asm("{ .reg .u64 t; cvta.to.shared.u64 t, %1; cvt.u32.u64 %0, t; }" : "=r"(a) : "l"(p));
    return a;
}
#define CP16(dst, src) asm volatile("cp.async.cg.shared.global [%0], [%1], 16;" :: "r"(dst), "l"(src))
#define CP_COMMIT() asm volatile("cp.async.commit_group;" ::: "memory")
#define CP_WAIT2()  asm volatile("cp.async.wait_group 2;" ::: "memory")

__device__ __forceinline__ void ldmat4(uint32_t* r, uint32_t addr){
    asm volatile("ldmatrix.sync.aligned.m8n8.x4.shared.b16 {%0,%1,%2,%3}, [%4];"
        : "=r"(r[0]),"=r"(r[1]),"=r"(r[2]),"=r"(r[3]) : "r"(addr));
}
__device__ __forceinline__ void mma_f16(float* c, const uint32_t* a, const uint32_t* b){
    asm volatile("mma.sync.aligned.m16n8k16.row.col.f32.f16.f16.f32 "
        "{%0,%1,%2,%3}, {%4,%5,%6,%7}, {%8,%9}, {%0,%1,%2,%3};"
        : "+f"(c[0]),"+f"(c[1]),"+f"(c[2]),"+f"(c[3])
        : "r"(a[0]),"r"(a[1]),"r"(a[2]),"r"(a[3]), "r"(b[0]),"r"(b[1]));
}

// MMA block with register-resident A-frags; B via LDSM from smem stage.
__device__ __forceinline__ void mma_block(const uint32_t a[2][4][4], uint32_t sb,
        int wn, int rA, int cAd, float acc[4][8][4]){
    uint32_t b[2][8][2];
#pragma unroll
    for (int ks = 0; ks < 2; ks++){
#pragma unroll
        for (int p = 0; p < 4; p++){
            uint32_t r[4];
            ldmat4(r, sb + (uint32_t)((64*wn + 16*p + rA)*STRB + (2*ks + cAd)*16));
            b[ks][2*p][0] = r[0]; b[ks][2*p+1][0] = r[1];
            b[ks][2*p][1] = r[2]; b[ks][2*p+1][1] = r[3];
        }
    }
#pragma unroll
    for (int ks = 0; ks < 2; ks++)
#pragma unroll
        for (int mt = 0; mt < 4; mt++)
#pragma unroll
            for (int nt = 0; nt < 8; nt++)
                mma_f16(acc[mt][nt], a[ks][mt], b[ks][nt]);
}

// ---------------------------------------------------------------------------
// Precompute: fp16 weights/M row-major; Q in fragment-major layout.
// Qf frag f = (tile t, kstep ks, lane l): 16B = 4 half2:
//   h0 = Q[t*16+r, ks*16+c..c+1], h1 = Q[t*16+r+8, c..c+1],
//   h2 = Q[t*16+r, c+8..c+9],     h3 = Q[t*16+r+8, c+8..c+9]
//   with r = l>>2, c = (l&3)*2.
// ---------------------------------------------------------------------------
__global__ void k_conv(const float* __restrict__ W1, const float* __restrict__ W2,
                       const float* __restrict__ Q,  const float* __restrict__ Maug){
    const int stride = gridDim.x * blockDim.x;
    const int i0 = blockIdx.x*blockDim.x + threadIdx.x;
    for (int i = i0; i < H1C*DD; i += stride) g_w1h[i] = __float2half(W1[i]);
    for (int i = i0; i < H2C*H1C; i += stride) g_w2h[i] = __float2half(W2[i]);
    for (int i = i0; i < NP*DD;  i += stride) g_mh[i] = __float2half(Maug[i]);
    for (int f = i0; f < 32*64*32; f += stride){
        const int t = f >> 11, ks = (f >> 5) & 63, l = f & 31;
        const int r = l >> 2, c = (l & 3) * 2;
        const float* q0 = Q + (size_t)(t*16 + r)     * DD + ks*16;
        const float* q8 = Q + (size_t)(t*16 + r + 8) * DD + ks*16;
        U4 v;
        v.h[0] = __floats2half2_rn(q0[c],   q0[c+1]);
        v.h[1] = __floats2half2_rn(q8[c],   q8[c+1]);
        v.h[2] = __floats2half2_rn(q0[c+8], q0[c+9]);
        v.h[3] = __floats2half2_rn(q8[c+8], q8[c+9]);
        g_qf[f] = v.u;
    }
}

__global__ void k_nop(){}   // fillers: keep k_layer1 at ncu's profiled index 3

// ---------------------------------------------------------------------------
// Layer 1: GEMM [262144 x 512], K=1024.  CTA 128x128, 128 thr, 2 CTAs/SM.
// A-frags built in registers from Qf + M(smem).  B staged via cp.async.
// smem: B 4 x 10240 + Mrow 2048 = 43008
// ---------------------------------------------------------------------------
#define L1_SMEM (4*10240 + 2048)
#define MOFF    (4*10240)

__global__ __launch_bounds__(128,2) void k_layer1(const float* __restrict__ b1)
{
    extern __shared__ __align__(16) char smem[];
    const int tid = threadIdx.x, lane = tid & 31, wid = tid >> 5;
    const int h0 = blockIdx.x * 128;
    const int r0 = blockIdx.y * 128;
    const int n  = r0 >> 9;
    const int m0 = r0 & 511;
    const int wm = wid & 1, wn = wid >> 1;
    const int rA = lane & 15, cAd = lane >> 4;
    const bool do_cost = (blockIdx.x == 0);

    const uint32_t sbase = smem_u32(smem);
    const uint32_t sBu = sbase;

    // M row -> smem (2 KB)
    ((uint4*)(smem + MOFF))[tid] = ((const uint4*)&g_mh[(size_t)n*DD])[tid];

    float acc[4][8][4];
#pragma unroll
    for (int i=0;i<4;i++)
#pragma unroll
    for (int j=0;j<8;j++)
#pragma unroll
    for (int k=0;k<4;k++) acc[i][j][k] = 0.f;
    float creg[4][2];
#pragma unroll
    for (int i=0;i<4;i++){ creg[i][0]=0.f; creg[i][1]=0.f; }

    auto fillB = [&](int c){
        const uint32_t s = sBu + (uint32_t)(c & 3) * 10240;
#pragma unroll
        for (int jj = 0; jj < 4; jj++){
            const int idx = tid + 128*jj;
            const int row = idx >> 2, ch = idx & 3;
            CP16(s + (uint32_t)(row*STRB + ch*16),
                 g_w1h + (size_t)(h0 + row)*DD + c*32 + ch*8);
        }
    };

    fillB(0); CP_COMMIT();
    fillB(1); CP_COMMIT();
    fillB(2); CP_COMMIT();

    const int qt0 = (m0 + 64*wm) >> 4;   // Qf tile base for this warp

    for (int c = 0; c < 32; c++){
        // issue A-frag source loads early (latency covered by the stage barrier)
        uint4 qf[8];
#pragma unroll
        for (int mt = 0; mt < 4; mt++)
#pragma unroll
            for (int ks = 0; ks < 2; ks++)
                qf[mt*2+ks] = g_qf[((qt0 + mt)*64 + (c*2 + ks))*32 + lane];

        CP_WAIT2(); __syncthreads();
        if (c + 3 < 32) fillB(c + 3);
        CP_COMMIT();

        // build A-frags: (q - m)^2, half2
        uint32_t afr[2][4][4];
#pragma unroll
        for (int ks = 0; ks < 2; ks++){
            const int cb = (c*32 + ks*16 + (lane&3)*2)*2;
            const __half2 mlo = *(const __half2*)(smem + MOFF + cb);
            const __half2 mhi = *(const __half2*)(smem + MOFF + cb + 16);
#pragma unroll
            for (int mt = 0; mt < 4; mt++){
                U4 q; q.u = qf[mt*2+ks];
                __half2 d, s0, s1, s2, s3;
                d = __hsub2(q.h[0], mlo); s0 = __hmul2(d,d);
                d = __hsub2(q.h[1], mlo); s1 = __hmul2(d,d);
                d = __hsub2(q.h[2], mhi); s2 = __hmul2(d,d);
                d = __hsub2(q.h[3], mhi); s3 = __hmul2(d,d);
                afr[ks][mt][0] = *(uint32_t*)&s0;
                afr[ks][mt][1] = *(uint32_t*)&s1;
                afr[ks][mt][2] = *(uint32_t*)&s2;
                afr[ks][mt][3] = *(uint32_t*)&s3;
                if (do_cost){
                    float2 f0 = __half22float2(s0), f1 = __half22float2(s1);
                    float2 f2 = __half22float2(s2), f3 = __half22float2(s3);
                    creg[mt][0] += (f0.x + f0.y) + (f2.x + f2.y);
                    creg[mt][1] += (f1.x + f1.y) + (f3.x + f3.y);
                }
            }
        }
        mma_block(afr, sBu + (uint32_t)(c & 3)*10240, wn, rA, cAd, acc);
    }

    // fused cost: reduce over the 4 lanes sharing each row (lane&3 varies)
    if (do_cost){
#pragma unroll
        for (int mt = 0; mt < 4; mt++)
#pragma unroll
            for (int hh = 0; hh < 2; hh++){
                float v = creg[mt][hh];
                v += __shfl_xor_sync(0xffffffffu, v, 1);
                v += __shfl_xor_sync(0xffffffffu, v, 2);
                if ((lane & 3) == 0)
                    g_cost[n*MP + m0 + 64*wm + 16*mt + 8*hh + (lane>>2)] = v;
            }
    }

    // epilogue: bias + lrelu, store h1 in FRAGMENT-MAJOR layout
#pragma unroll
    for (int mt = 0; mt < 4; mt++){
        const size_t rt = (size_t)((r0 + 64*wm + 16*mt) >> 4);
#pragma unroll
        for (int ntp = 0; ntp < 4; ntp++){
            const int kstep = (h0 + 64*wn + 16*ntp) >> 4;
            const int col0 = h0 + 64*wn + 16*ntp + 2*(lane&3);
            const float b00 = b1[col0],   b01 = b1[col0+1];
            const float b08 = b1[col0+8], b09 = b1[col0+9];
            U4 v;
            v.h[0] = __floats2half2_rn(lrelu(acc[mt][2*ntp][0]+b00),   lrelu(acc[mt][2*ntp][1]+b01));
            v.h[1] = __floats2half2_rn(lrelu(acc[mt][2*ntp][2]+b00),   lrelu(acc[mt][2*ntp][3]+b01));
            v.h[2] = __floats2half2_rn(lrelu(acc[mt][2*ntp+1][0]+b08), lrelu(acc[mt][2*ntp+1][1]+b09));
            v.h[3] = __floats2half2_rn(lrelu(acc[mt][2*ntp+1][2]+b08), lrelu(acc[mt][2*ntp+1][3]+b09));
            g_h1f[(rt*32 + kstep)*32 + lane] = v.u;
        }
    }
}

// ---------------------------------------------------------------------------
// Layer 2+3: GEMM [262144 x 256], K=512.  CTA 128x128, 2 CTAs/SM.
// A-frags LDG'd directly from fragment-major g_h1f.  B (W2) staged via cp.async.
// Epilogue: bias + lrelu + W3 dot -> per-strip partial logit.
// smem: B 4 x 10240 = 40960
// ---------------------------------------------------------------------------
#define L2_SMEM (4*10240)

__global__ __launch_bounds__(128,2) void k_layer2(
    const float* __restrict__ b2, const float* __restrict__ W3)
{
    extern __shared__ __align__(16) char smem[];
    const int tid = threadIdx.x, lane = tid & 31, wid = tid >> 5;
    const int h0 = blockIdx.x * 128;       // 2 col blocks
    const int r0 = blockIdx.y * 128;
    const int wm = wid & 1, wn = wid >> 1;
    const int rA = lane & 15, cAd = lane >> 4;

    const uint32_t sbase = smem_u32(smem);
    const uint32_t sBu = sbase;

    float acc[4][8][4];
#pragma unroll
    for (int i=0;i<4;i++)
#pragma unroll
    for (int j=0;j<8;j++)
#pragma unroll
    for (int k=0;k<4;k++) acc[i][j][k] = 0.f;

    auto fillB = [&](int c){
        const uint32_t s = sBu + (uint32_t)(c & 3) * 10240;
#pragma unroll
        for (int jj = 0; jj < 4; jj++){
            const int idx = tid + 128*jj;
            const int row = idx >> 2, ch = idx & 3;
            CP16(s + (uint32_t)(row*STRB + ch*16),
                 g_w2h + (size_t)(h0 + row)*H1C + c*32 + ch*8);
        }
    };

    fillB(0); CP_COMMIT();
    fillB(1); CP_COMMIT();
    fillB(2); CP_COMMIT();

    const size_t rt0 = (size_t)((r0 + 64*wm) >> 4);

    for (int c = 0; c < 16; c++){
        uint32_t afr[2][4][4];
#pragma unroll
        for (int mt = 0; mt < 4; mt++)
#pragma unroll
            for (int ks = 0; ks < 2; ks++){
                const uint4 q = g_h1f[((rt0 + mt)*32 + (c*2 + ks))*32 + lane];
                afr[ks][mt][0] = q.x; afr[ks][mt][1] = q.y;
                afr[ks][mt][2] = q.z; afr[ks][mt][3] = q.w;
            }
        CP_WAIT2(); __syncthreads();
        if (c + 3 < 16) fillB(c + 3);
        CP_COMMIT();
        mma_block(afr, sBu + (uint32_t)(c & 3)*10240, wn, rA, cAd, acc);
    }

    // epilogue: bias + lrelu + W3 dot
    const int g = lane >> 2, tg = lane & 3;
    float dot[4][2];
#pragma unroll
    for (int mt=0; mt<4; mt++){ dot[mt][0]=0.f; dot[mt][1]=0.f; }
#pragma unroll
    for (int nt = 0; nt < 8; nt++){
        const int col = h0 + 64*wn + 8*nt + 2*tg;
        const float b0v = b2[col], b1v = b2[col+1];
        const float w0 = W3[col],  w1 = W3[col+1];
#pragma unroll
        for (int mt = 0; mt < 4; mt++){
            dot[mt][0] += lrelu(acc[mt][nt][0]+b0v)*w0 + lrelu(acc[mt][nt][1]+b1v)*w1;
            dot[mt][1] += lrelu(acc[mt][nt][2]+b0v)*w0 + lrelu(acc[mt][nt][3]+b1v)*w1;
        }
    }
    float* spart = (float*)smem;   // [128][2]
    __syncthreads();
#pragma unroll
    for (int mt = 0; mt < 4; mt++)
#pragma unroll
        for (int hh = 0; hh < 2; hh++){
            float v = dot[mt][hh];
            v += __shfl_xor_sync(0xffffffffu, v, 1);
            v += __shfl_xor_sync(0xffffffffu, v, 2);
            if (tg == 0) spart[(64*wm + 16*mt + 8*hh + g)*2 + wn] = v;
        }
    __syncthreads();
    if (tid < 128){
        g_dpart[(size_t)(r0 + tid)*2 + blockIdx.x] = spart[tid*2+0] + spart[tid*2+1];
    }
}

// ---------------------------------------------------------------------------
// Softmax over n (per m) + weighted reductions
// ---------------------------------------------------------------------------
__global__ __launch_bounds__(512) void k_reduce(
    const int* __restrict__ nfg_p, const float* __restrict__ b3,
    float* __restrict__ out)
{
    __shared__ float sm[512];
    const int m = blockIdx.x, n = threadIdx.x;
    const int r = n*MP + m;
    const float v = -(g_dpart[(size_t)r*2] + g_dpart[(size_t)r*2+1] + b3[0]);

    sm[n] = v; __syncthreads();
    for (int s = 256; s; s >>= 1) {
        if (n < s) sm[n] = fmaxf(sm[n], sm[n + s]);
        __syncthreads();
    }
    const float mx = sm[0]; __syncthreads();

    const float p = expf(v - mx);
    sm[n] = p; __syncthreads();
    for (int s = 256; s; s >>= 1) {
        if (n < s) sm[n] += sm[n + s];
        __syncthreads();
    }
    const float Z = sm[0]; __syncthreads();

    const float sval = g_cost[r] * (p / Z);
    sm[n] = sval; __syncthreads();
    for (int s = 256; s; s >>= 1) {
        if (n < s) sm[n] += sm[n + s];
        __syncthreads();
    }
    const float score = sm[0]; __syncthreads();

    const int nfg = *nfg_p;
    sm[n] = (n < nfg) ? sval : 0.f; __syncthreads();
    for (int s = 256; s; s >>= 1) {
        if (n < s) sm[n] += sm[n + s];
        __syncthreads();
    }
    if (n == 0) {
        out[m]      = score;
        out[MP + m] = sm[0];
    }
}

// ---------------------------------------------------------------------------
extern "C" void kernel_launch(void* const* d_in, const int* in_sizes, int n_in,
                              void* d_out, int out_size)
{
    const float* Maug = (const float*)d_in[0];
    const float* Q    = (const float*)d_in[1];
    const float* W1   = (const float*)d_in[2];
    const float* b1   = (const float*)d_in[3];
    const float* W2   = (const float*)d_in[4];
    const float* b2   = (const float*)d_in[5];
    const float* W3   = (const float*)d_in[6];
    const float* b3   = (const float*)d_in[7];
    const int*   nfg  = (const int*)d_in[8];
    float* out = (float*)d_out;

    cudaFuncSetAttribute(k_layer1, cudaFuncAttributeMaxDynamicSharedMemorySize, L1_SMEM);
    cudaFuncSetAttribute(k_layer2, cudaFuncAttributeMaxDynamicSharedMemorySize, L2_SMEM);

    k_conv  <<<512, 256>>>(W1, W2, Q, Maug);
    k_nop   <<<1, 32>>>();
    k_nop   <<<1, 32>>>();
    k_layer1<<<dim3(H1C/128, NPAIR/128), 128, L1_SMEM>>>(b1);
    k_layer2<<<dim3(H2C/128, NPAIR/128), 128, L2_SMEM>>>(b2, W3);
    k_reduce<<<MP, 512>>>(nfg, b3, out);
}

// round 9
// speedup vs baseline: 1.1324x; 1.0685x over previous
#include <cuda_runtime.h>
#include <cuda_fp16.h>
#include <stdint.h>
#include <math.h>

#define NP 512
#define MP 512
#define DD 1024
#define H1C 512
#define H2C 256
#define NPAIR (NP*MP)
#define STRB 80   // bytes per 32-half smem row (64B data + 16B pad)

// Scratch
__device__ uint4  g_h1f[(size_t)16384 * 32 * 32]; // h1 in fragment-major (256 MB)
__device__ uint4  g_qf[32 * 64 * 32];             // Q fragment-major (1 MB)
__device__ __half g_w1h[H1C * DD];
__device__ __half g_w2h[H2C * H1C];
__device__ __half g_mh[NP * DD];
__device__ float  g_dpart[(size_t)NPAIR * 2];
__device__ float  g_cost[NPAIR];

union U4 { uint4 u; __half2 h[4]; };

__device__ __forceinline__ float lrelu(float x){ return x >= 0.f ? x : 0.01f*x; }
__device__ __forceinline__ uint32_t smem_u32(const void* p){
    uint32_t a;
    asm("{ .reg .u64 t; cvta.to.shared.u64 t, %1; cvt.u32.u64 %0, t; }" : "=r"(a) : "l"(p));
    return a;
}
#define CP16(dst, src) asm volatile("cp.async.cg.shared.global [%0], [%1], 16;" :: "r"(dst), "l"(src))
#define CP_COMMIT() asm volatile("cp.async.commit_group;" ::: "memory")
#define CP_WAIT2()  asm volatile("cp.async.wait_group 2;" ::: "memory")

__device__ __forceinline__ void ldmat4(uint32_t* r, uint32_t addr){
    asm volatile("ldmatrix.sync.aligned.m8n8.x4.shared.b16 {%0,%1,%2,%3}, [%4];"
        : "=r"(r[0]),"=r"(r[1]),"=r"(r[2]),"=r"(r[3]) : "r"(addr));
}
__device__ __forceinline__ void mma_f16(float* c, const uint32_t* a, const uint32_t* b){
    asm volatile("mma.sync.aligned.m16n8k16.row.col.f32.f16.f16.f32 "
        "{%0,%1,%2,%3}, {%4,%5,%6,%7}, {%8,%9}, {%0,%1,%2,%3};"
        : "+f"(c[0]),"+f"(c[1]),"+f"(c[2]),"+f"(c[3])
        : "r"(a[0]),"r"(a[1]),"r"(a[2]),"r"(a[3]), "r"(b[0]),"r"(b[1]));
}

// MMA for warp tile 32x64: A-frags in registers, B via LDSM per k-step.
__device__ __forceinline__ void mma_block32(const uint32_t a[2][2][4], uint32_t sb,
        int wn, int rA, int cAd, float acc[2][8][4]){
#pragma unroll
    for (int ks = 0; ks < 2; ks++){
        uint32_t b[8][2];
#pragma unroll
        for (int p = 0; p < 4; p++){
            uint32_t r[4];
            ldmat4(r, sb + (uint32_t)((64*wn + 16*p + rA)*STRB + (2*ks + cAd)*16));
            b[2*p][0] = r[0]; b[2*p+1][0] = r[1];
            b[2*p][1] = r[2]; b[2*p+1][1] = r[3];
        }
#pragma unroll
        for (int mt = 0; mt < 2; mt++)
#pragma unroll
            for (int nt = 0; nt < 8; nt++)
                mma_f16(acc[mt][nt], a[ks][mt], b[nt]);
    }
}

// ---------------------------------------------------------------------------
// Precompute: fp16 weights/M row-major; Q in fragment-major layout.
// ---------------------------------------------------------------------------
__global__ void k_conv(const float* __restrict__ W1, const float* __restrict__ W2,
                       const float* __restrict__ Q,  const float* __restrict__ Maug){
    const int stride = gridDim.x * blockDim.x;
    const int i0 = blockIdx.x*blockDim.x + threadIdx.x;
    for (int i = i0; i < H1C*DD; i += stride) g_w1h[i] = __float2half(W1[i]);
    for (int i = i0; i < H2C*H1C; i += stride) g_w2h[i] = __float2half(W2[i]);
    for (int i = i0; i < NP*DD;  i += stride) g_mh[i] = __float2half(Maug[i]);
    for (int f = i0; f < 32*64*32; f += stride){
        const int t = f >> 11, ks = (f >> 5) & 63, l = f & 31;
        const int r = l >> 2, c = (l & 3) * 2;
        const float* q0 = Q + (size_t)(t*16 + r)     * DD + ks*16;
        const float* q8 = Q + (size_t)(t*16 + r + 8) * DD + ks*16;
        U4 v;
        v.h[0] = __floats2half2_rn(q0[c],   q0[c+1]);
        v.h[1] = __floats2half2_rn(q8[c],   q8[c+1]);
        v.h[2] = __floats2half2_rn(q0[c+8], q0[c+9]);
        v.h[3] = __floats2half2_rn(q8[c+8], q8[c+9]);
        g_qf[f] = v.u;
    }
}

__global__ void k_nop(){}   // fillers: keep k_layer1 at ncu's profiled index 3

// ---------------------------------------------------------------------------
// Layer 1: GEMM [262144 x 512], K=1024.  CTA 128x128, 256 thr (8 warps of
// 32x64), 2 CTAs/SM -> 16 warps/SM.  A-frags in registers from Qf + M(smem).
// smem: B 4 x 10240 + Mrow 2048 = 43008
// ---------------------------------------------------------------------------
#define L1_SMEM (4*10240 + 2048)
#define MOFF    (4*10240)

__global__ __launch_bounds__(256,2) void k_layer1(const float* __restrict__ b1)
{
    extern __shared__ __align__(16) char smem[];
    const int tid = threadIdx.x, lane = tid & 31, wid = tid >> 5;
    const int h0 = blockIdx.x * 128;
    const int r0 = blockIdx.y * 128;
    const int n  = r0 >> 9;
    const int m0 = r0 & 511;
    const int wm = wid & 3, wn = wid >> 2;
    const int rA = lane & 15, cAd = lane >> 4;
    const bool do_cost = (blockIdx.x == 0) && (wn == 0);

    const uint32_t sbase = smem_u32(smem);
    const uint32_t sBu = sbase;

    // M row -> smem (2 KB = 128 uint4)
    if (tid < 128)
        ((uint4*)(smem + MOFF))[tid] = ((const uint4*)&g_mh[(size_t)n*DD])[tid];

    float acc[2][8][4];
#pragma unroll
    for (int i=0;i<2;i++)
#pragma unroll
    for (int j=0;j<8;j++)
#pragma unroll
    for (int k=0;k<4;k++) acc[i][j][k] = 0.f;
    float creg[2][2];
#pragma unroll
    for (int i=0;i<2;i++){ creg[i][0]=0.f; creg[i][1]=0.f; }

    auto fillB = [&](int c){
        const uint32_t s = sBu + (uint32_t)(c & 3) * 10240;
#pragma unroll
        for (int jj = 0; jj < 2; jj++){
            const int idx = tid + 256*jj;
            const int row = idx >> 2, ch = idx & 3;
            CP16(s + (uint32_t)(row*STRB + ch*16),
                 g_w1h + (size_t)(h0 + row)*DD + c*32 + ch*8);
        }
    };

    fillB(0); CP_COMMIT();
    fillB(1); CP_COMMIT();
    fillB(2); CP_COMMIT();

    const int qt0 = (m0 + 32*wm) >> 4;   // Qf tile base for this warp

    for (int c = 0; c < 32; c++){
        // A-frag source loads (latency covered by stage barrier + 16 warps/SM)
        uint4 qf[4];
#pragma unroll
        for (int mt = 0; mt < 2; mt++)
#pragma unroll
            for (int ks = 0; ks < 2; ks++)
                qf[mt*2+ks] = g_qf[((qt0 + mt)*64 + (c*2 + ks))*32 + lane];

        CP_WAIT2(); __syncthreads();
        if (c + 3 < 32) fillB(c + 3);
        CP_COMMIT();

        // build A-frags: (q - m)^2, half2
        uint32_t afr[2][2][4];
#pragma unroll
        for (int ks = 0; ks < 2; ks++){
            const int cb = (c*32 + ks*16 + (lane&3)*2)*2;
            const __half2 mlo = *(const __half2*)(smem + MOFF + cb);
            const __half2 mhi = *(const __half2*)(smem + MOFF + cb + 16);
#pragma unroll
            for (int mt = 0; mt < 2; mt++){
                U4 q; q.u = qf[mt*2+ks];
                __half2 d, s0, s1, s2, s3;
                d = __hsub2(q.h[0], mlo); s0 = __hmul2(d,d);
                d = __hsub2(q.h[1], mlo); s1 = __hmul2(d,d);
                d = __hsub2(q.h[2], mhi); s2 = __hmul2(d,d);
                d = __hsub2(q.h[3], mhi); s3 = __hmul2(d,d);
                afr[ks][mt][0] = *(uint32_t*)&s0;
                afr[ks][mt][1] = *(uint32_t*)&s1;
                afr[ks][mt][2] = *(uint32_t*)&s2;
                afr[ks][mt][3] = *(uint32_t*)&s3;
                if (do_cost){
                    float2 f0 = __half22float2(s0), f1 = __half22float2(s1);
                    float2 f2 = __half22float2(s2), f3 = __half22float2(s3);
                    creg[mt][0] += (f0.x + f0.y) + (f2.x + f2.y);
                    creg[mt][1] += (f1.x + f1.y) + (f3.x + f3.y);
                }
            }
        }
        mma_block32(afr, sBu + (uint32_t)(c & 3)*10240, wn, rA, cAd, acc);
    }

    // fused cost: reduce over the 4 lanes sharing each row
    if (do_cost){
#pragma unroll
        for (int mt = 0; mt < 2; mt++)
#pragma unroll
            for (int hh = 0; hh < 2; hh++){
                float v = creg[mt][hh];
                v += __shfl_xor_sync(0xffffffffu, v, 1);
                v += __shfl_xor_sync(0xffffffffu, v, 2);
                if ((lane & 3) == 0)
                    g_cost[n*MP + m0 + 32*wm + 16*mt + 8*hh + (lane>>2)] = v;
            }
    }

    // epilogue: bias + lrelu, store h1 in FRAGMENT-MAJOR layout
#pragma unroll
    for (int mt = 0; mt < 2; mt++){
        const size_t rt = (size_t)((r0 + 32*wm + 16*mt) >> 4);
#pragma unroll
        for (int ntp = 0; ntp < 4; ntp++){
            const int kstep = (h0 + 64*wn + 16*ntp) >> 4;
            const int col0 = h0 + 64*wn + 16*ntp + 2*(lane&3);
            const float b00 = b1[col0],   b01 = b1[col0+1];
            const float b08 = b1[col0+8], b09 = b1[col0+9];
            U4 v;
            v.h[0] = __floats2half2_rn(lrelu(acc[mt][2*ntp][0]+b00),   lrelu(acc[mt][2*ntp][1]+b01));
            v.h[1] = __floats2half2_rn(lrelu(acc[mt][2*ntp][2]+b00),   lrelu(acc[mt][2*ntp][3]+b01));
            v.h[2] = __floats2half2_rn(lrelu(acc[mt][2*ntp+1][0]+b08), lrelu(acc[mt][2*ntp+1][1]+b09));
            v.h[3] = __floats2half2_rn(lrelu(acc[mt][2*ntp+1][2]+b08), lrelu(acc[mt][2*ntp+1][3]+b09));
            g_h1f[(rt*32 + kstep)*32 + lane] = v.u;
        }
    }
}

// ---------------------------------------------------------------------------
// Layer 2+3: GEMM [262144 x 256], K=512.  CTA 128x128, 256 thr, 2 CTAs/SM.
// A-frags LDG'd from fragment-major g_h1f.  Epilogue: bias+lrelu+W3 dot.
// smem: B 4 x 10240 = 40960
// ---------------------------------------------------------------------------
#define L2_SMEM (4*10240)

__global__ __launch_bounds__(256,2) void k_layer2(
    const float* __restrict__ b2, const float* __restrict__ W3)
{
    extern __shared__ __align__(16) char smem[];
    const int tid = threadIdx.x, lane = tid & 31, wid = tid >> 5;
    const int h0 = blockIdx.x * 128;       // 2 col blocks
    const int r0 = blockIdx.y * 128;
    const int wm = wid & 3, wn = wid >> 2;
    const int rA = lane & 15, cAd = lane >> 4;

    const uint32_t sbase = smem_u32(smem);
    const uint32_t sBu = sbase;

    float acc[2][8][4];
#pragma unroll
    for (int i=0;i<2;i++)
#pragma unroll
    for (int j=0;j<8;j++)
#pragma unroll
    for (int k=0;k<4;k++) acc[i][j][k] = 0.f;

    auto fillB = [&](int c){
        const uint32_t s = sBu + (uint32_t)(c & 3) * 10240;
#pragma unroll
        for (int jj = 0; jj < 2; jj++){
            const int idx = tid + 256*jj;
            const int row = idx >> 2, ch = idx & 3;
            CP16(s + (uint32_t)(row*STRB + ch*16),
                 g_w2h + (size_t)(h0 + row)*H1C + c*32 + ch*8);
        }
    };

    fillB(0); CP_COMMIT();
    fillB(1); CP_COMMIT();
    fillB(2); CP_COMMIT();

    const size_t rt0 = (size_t)((r0 + 32*wm) >> 4);

    for (int c = 0; c < 16; c++){
        uint32_t afr[2][2][4];
#pragma unroll
        for (int mt = 0; mt < 2; mt++)
#pragma unroll
            for (int ks = 0; ks < 2; ks++){
                const uint4 q = g_h1f[((rt0 + mt)*32 + (c*2 + ks))*32 + lane];
                afr[ks][mt][0] = q.x; afr[ks][mt][1] = q.y;
                afr[ks][mt][2] = q.z; afr[ks][mt][3] = q.w;
            }
        CP_WAIT2(); __syncthreads();
        if (c + 3 < 16) fillB(c + 3);
        CP_COMMIT();
        mma_block32(afr, sBu + (uint32_t)(c & 3)*10240, wn, rA, cAd, acc);
    }

    // epilogue: bias + lrelu + W3 dot
    const int g = lane >> 2, tg = lane & 3;
    float dot[2][2];
#pragma unroll
    for (int mt=0; mt<2; mt++){ dot[mt][0]=0.f; dot[mt][1]=0.f; }
#pragma unroll
    for (int nt = 0; nt < 8; nt++){
        const int col = h0 + 64*wn + 8*nt + 2*tg;
        const float b0v = b2[col], b1v = b2[col+1];
        const float w0 = W3[col],  w1 = W3[col+1];
#pragma unroll
        for (int mt = 0; mt < 2; mt++){
            dot[mt][0] += lrelu(acc[mt][nt][0]+b0v)*w0 + lrelu(acc[mt][nt][1]+b1v)*w1;
            dot[mt][1] += lrelu(acc[mt][nt][2]+b0v)*w0 + lrelu(acc[mt][nt][3]+b1v)*w1;
        }
    }
    float* spart = (float*)smem;   // [128][2]
    __syncthreads();
#pragma unroll
    for (int mt = 0; mt < 2; mt++)
#pragma unroll
        for (int hh = 0; hh < 2; hh++){
            float v = dot[mt][hh];
            v += __shfl_xor_sync(0xffffffffu, v, 1);
            v += __shfl_xor_sync(0xffffffffu, v, 2);
            if (tg == 0) spart[(32*wm + 16*mt + 8*hh + g)*2 + wn] = v;
        }
    __syncthreads();
    if (tid < 128){
        g_dpart[(size_t)(r0 + tid)*2 + blockIdx.x] = spart[tid*2+0] + spart[tid*2+1];
    }
}

// ---------------------------------------------------------------------------
// Softmax over n (per m) + weighted reductions
// ---------------------------------------------------------------------------
__global__ __launch_bounds__(512) void k_reduce(
    const int* __restrict__ nfg_p, const float* __restrict__ b3,
    float* __restrict__ out)
{
    __shared__ float sm[512];
    const int m = blockIdx.x, n = threadIdx.x;
    const int r = n*MP + m;
    const float v = -(g_dpart[(size_t)r*2] + g_dpart[(size_t)r*2+1] + b3[0]);

    sm[n] = v; __syncthreads();
    for (int s = 256; s; s >>= 1) {
        if (n < s) sm[n] = fmaxf(sm[n], sm[n + s]);
        __syncthreads();
    }
    const float mx = sm[0]; __syncthreads();

    const float p = expf(v - mx);
    sm[n] = p; __syncthreads();
    for (int s = 256; s; s >>= 1) {
        if (n < s) sm[n] += sm[n + s];
        __syncthreads();
    }
    const float Z = sm[0]; __syncthreads();

    const float sval = g_cost[r] * (p / Z);
    sm[n] = sval; __syncthreads();
    for (int s = 256; s; s >>= 1) {
        if (n < s) sm[n] += sm[n + s];
        __syncthreads();
    }
    const float score = sm[0]; __syncthreads();

    const int nfg = *nfg_p;
    sm[n] = (n < nfg) ? sval : 0.f; __syncthreads();
    for (int s = 256; s; s >>= 1) {
        if (n < s) sm[n] += sm[n + s];
        __syncthreads();
    }
    if (n == 0) {
        out[m]      = score;
        out[MP + m] = sm[0];
    }
}

// ---------------------------------------------------------------------------
extern "C" void kernel_launch(void* const* d_in, const int* in_sizes, int n_in,
                              void* d_out, int out_size)
{
    const float* Maug = (const float*)d_in[0];
    const float* Q    = (const float*)d_in[1];
    const float* W1   = (const float*)d_in[2];
    const float* b1   = (const float*)d_in[3];
    const float* W2   = (const float*)d_in[4];
    const float* b2   = (const float*)d_in[5];
    const float* W3   = (const float*)d_in[6];
    const float* b3   = (const float*)d_in[7];
    const int*   nfg  = (const int*)d_in[8];
    float* out = (float*)d_out;

    cudaFuncSetAttribute(k_layer1, cudaFuncAttributeMaxDynamicSharedMemorySize, L1_SMEM);
    cudaFuncSetAttribute(k_layer2, cudaFuncAttributeMaxDynamicSharedMemorySize, L2_SMEM);

    k_conv  <<<512, 256>>>(W1, W2, Q, Maug);
    k_nop   <<<1, 32>>>();
    k_nop   <<<1, 32>>>();
    k_layer1<<<dim3(H1C/128, NPAIR/128), 256, L1_SMEM>>>(b1);
    k_layer2<<<dim3(H2C/128, NPAIR/128), 256, L2_SMEM>>>(b2, W3);
    k_reduce<<<MP, 512>>>(nfg, b3, out);
}